// round 2
// baseline (speedup 1.0000x reference)
#include <cuda_runtime.h>

// LSTM_80582176407707: 2-layer LSTM, persistent fp32 kernel.
// B=32, T=2048, I=256, H=512, O=256.
//
// Strategy: one persistent kernel, 128 CTAs (1/SM), all weights SMEM-resident.
// Each CTA owns 4 hidden units (16 gate rows) per layer. Per timestep:
//   phase1: gates0 = [x_t | h0] @ W0_slice^T  -> elementwise -> h0 (double buffered)
//   grid barrier
//   phase2: gates1 = [h0_new | h1] @ W1_slice^T -> elementwise -> h1
//   grid barrier
// Cell state c lives in registers of the owning threads. Final FC at the end.

#define BATCH   32
#define TSTEPS  2048
#define INDIM   256
#define HID     512
#define ODIM    256
#define NCTA    128
#define NTH     256
#define HXW     516      // padded h/x staging row (floats); 516/4=129 f4 (odd -> conflict-free)
#define HXW4    129
#define W0K     768      // 256 (x) + 512 (h0)
#define W1K     1024     // 512 (h0) + 512 (h1)
#define W0STR4  (W0K/4)  // 192
#define W1STR4  (W1K/4)  // 256

// Persistent state (scratch via __device__ globals, per the harness rules).
__device__ float g_h0[2][BATCH * HID];
__device__ float g_h1[2][BATCH * HID];
__device__ unsigned g_cnt = 0;
__device__ volatile unsigned g_gen = 0;

__device__ __forceinline__ void grid_barrier() {
    __syncthreads();
    if (threadIdx.x == 0) {
        __threadfence();
        unsigned gen = g_gen;
        if (atomicAdd(&g_cnt, 1u) == NCTA - 1u) {
            g_cnt = 0u;
            __threadfence();
            g_gen = gen + 1u;
        } else {
            while (g_gen == gen) { __nanosleep(32); }
        }
        __threadfence();
    }
    __syncthreads();
}

__device__ __forceinline__ float sigf(float x) {
    return 1.0f / (1.0f + __expf(-x));
}

// Accumulate 4 gate rows (l0..l3, warp-broadcast weight reads) against the
// staged activation chunk in hx4. Warps 0-3 take the low K-half, 4-7 the high.
#define GEMM_CHUNK(WQ, WSTR, WB, NQH)                                          \
    do {                                                                       \
        const int kk0 = half * (NQH);                                          \
        const float4* hp  = hx4 + b * HXW4 + kk0;                              \
        const float4* wp0 = (WQ) + l0 * (WSTR) + (WB) + kk0;                   \
        const float4* wp1 = (WQ) + l1 * (WSTR) + (WB) + kk0;                   \
        const float4* wp2 = (WQ) + l2 * (WSTR) + (WB) + kk0;                   \
        const float4* wp3 = (WQ) + l3 * (WSTR) + (WB) + kk0;                   \
        _Pragma("unroll 8")                                                    \
        for (int kq = 0; kq < (NQH); ++kq) {                                   \
            float4 hv = hp[kq];                                                \
            float4 w;                                                          \
            w = wp0[kq];                                                       \
            a0 = fmaf(hv.x, w.x, a0); a0 = fmaf(hv.y, w.y, a0);                \
            a0 = fmaf(hv.z, w.z, a0); a0 = fmaf(hv.w, w.w, a0);                \
            w = wp1[kq];                                                       \
            a1 = fmaf(hv.x, w.x, a1); a1 = fmaf(hv.y, w.y, a1);                \
            a1 = fmaf(hv.z, w.z, a1); a1 = fmaf(hv.w, w.w, a1);                \
            w = wp2[kq];                                                       \
            a2 = fmaf(hv.x, w.x, a2); a2 = fmaf(hv.y, w.y, a2);                \
            a2 = fmaf(hv.z, w.z, a2); a2 = fmaf(hv.w, w.w, a2);                \
            w = wp3[kq];                                                       \
            a3 = fmaf(hv.x, w.x, a3); a3 = fmaf(hv.y, w.y, a3);                \
            a3 = fmaf(hv.z, w.z, a3); a3 = fmaf(hv.w, w.w, a3);                \
        }                                                                      \
    } while (0)

__global__ __launch_bounds__(NTH, 1) void lstm_persistent_kernel(
    const float* __restrict__ x,
    const float* __restrict__ Wih0, const float* __restrict__ Whh0,
    const float* __restrict__ bih0, const float* __restrict__ bhh0,
    const float* __restrict__ Wih1, const float* __restrict__ Whh1,
    const float* __restrict__ bih1, const float* __restrict__ bhh1,
    const float* __restrict__ fcw,  const float* __restrict__ fcb,
    float* __restrict__ out)
{
    extern __shared__ float smem[];
    float* W0    = smem;                  // [16][768]
    float* W1    = W0 + 16 * W0K;         // [16][1024]
    float* hx    = W1 + 16 * W1K;         // [32][516]
    float* red   = hx + BATCH * HXW;      // [128][4]
    float* bias0 = red + 512;             // [16]
    float* bias1 = bias0 + 16;            // [16]

    const int tid  = threadIdx.x;
    const int r    = blockIdx.x;
    const int b    = tid & 31;            // batch lane
    const int jg   = (tid >> 5) & 3;      // which hidden unit (of this CTA's 4)
    const int half = tid >> 7;            // K-split half (0 or 1)

    // ---- Load this CTA's weight row slices into SMEM (one time) ----
    // Local row l (0..15) -> gate-type t=l>>2 (i,f,g,o), unit q=l&3.
    // Global gate row g = 512*t + 4*r + q.
    for (int idx = tid; idx < 16 * W0K; idx += NTH) {
        int l = idx / W0K, k = idx - l * W0K;
        int g = ((l >> 2) << 9) + (r << 2) + (l & 3);
        W0[idx] = (k < INDIM) ? Wih0[g * INDIM + k] : Whh0[g * HID + (k - INDIM)];
    }
    for (int idx = tid; idx < 16 * W1K; idx += NTH) {
        int l = idx >> 10, k = idx & 1023;
        int g = ((l >> 2) << 9) + (r << 2) + (l & 3);
        W1[idx] = (k < HID) ? Wih1[g * HID + k] : Whh1[g * HID + (k - HID)];
    }
    if (tid < 16) {
        int l = tid;
        int g = ((l >> 2) << 9) + (r << 2) + (l & 3);
        bias0[l] = bih0[g] + bhh0[g];
        bias1[l] = bih1[g] + bhh1[g];
    }
    // Zero initial hidden state (buffer 0) for this CTA's units.
    if (tid < 128) {
        int q = tid >> 5, bb = tid & 31;
        int u = (r << 2) + q;
        g_h0[0][bb * HID + u] = 0.0f;
        g_h1[0][bb * HID + u] = 0.0f;
    }
    grid_barrier();

    float4* hx4 = (float4*)hx;
    const float4* Wq0 = (const float4*)W0;
    const float4* Wq1 = (const float4*)W1;
    const int l0 = jg, l1 = jg + 4, l2 = jg + 8, l3 = jg + 12;

    float c0 = 0.0f, c1 = 0.0f;   // cell state (valid in half==0 threads)

    for (int t = 0; t < TSTEPS; ++t) {
        const int p = t & 1;
        float a0 = 0.0f, a1 = 0.0f, a2 = 0.0f, a3 = 0.0f;

        // ---------------- Layer 0 ----------------
        // stage x_t : [32 b][64 f4]
        {
            const float4* xs = (const float4*)x;
            #pragma unroll
            for (int i = 0; i < 8; ++i) {
                int idx = i * NTH + tid;         // 0..2047
                int bb = idx >> 6, kq = idx & 63;
                hx4[bb * HXW4 + kq] =
                    __ldg(&xs[bb * (TSTEPS * INDIM / 4) + t * (INDIM / 4) + kq]);
            }
        }
        __syncthreads();
        GEMM_CHUNK(Wq0, W0STR4, 0, 32);          // x part, K=256
        __syncthreads();
        // stage h0(t-1) : [32 b][128 f4]
        {
            const float4* src = (const float4*)g_h0[p];
            #pragma unroll
            for (int i = 0; i < 16; ++i) {
                int idx = i * NTH + tid;         // 0..4095
                int bb = idx >> 7, kq = idx & 127;
                hx4[bb * HXW4 + kq] = __ldcg(&src[bb * 128 + kq]);
            }
        }
        __syncthreads();
        GEMM_CHUNK(Wq0, W0STR4, 64, 64);         // h0 part, K=512
        __syncthreads();
        if (half) {
            red[(tid - 128) * 4 + 0] = a0; red[(tid - 128) * 4 + 1] = a1;
            red[(tid - 128) * 4 + 2] = a2; red[(tid - 128) * 4 + 3] = a3;
        }
        __syncthreads();
        if (!half) {
            a0 += red[tid * 4 + 0] + bias0[l0];
            a1 += red[tid * 4 + 1] + bias0[l1];
            a2 += red[tid * 4 + 2] + bias0[l2];
            a3 += red[tid * 4 + 3] + bias0[l3];
            float ig = sigf(a0), fg = sigf(a1), gg = tanhf(a2), og = sigf(a3);
            c0 = fg * c0 + ig * gg;
            g_h0[1 - p][b * HID + (r << 2) + jg] = og * tanhf(c0);
        }
        grid_barrier();

        // ---------------- Layer 1 ----------------
        a0 = 0.0f; a1 = 0.0f; a2 = 0.0f; a3 = 0.0f;
        {
            const float4* src = (const float4*)g_h0[1 - p];
            #pragma unroll
            for (int i = 0; i < 16; ++i) {
                int idx = i * NTH + tid;
                int bb = idx >> 7, kq = idx & 127;
                hx4[bb * HXW4 + kq] = __ldcg(&src[bb * 128 + kq]);
            }
        }
        __syncthreads();
        GEMM_CHUNK(Wq1, W1STR4, 0, 64);          // W_ih1 part, K=512
        __syncthreads();
        {
            const float4* src = (const float4*)g_h1[p];
            #pragma unroll
            for (int i = 0; i < 16; ++i) {
                int idx = i * NTH + tid;
                int bb = idx >> 7, kq = idx & 127;
                hx4[bb * HXW4 + kq] = __ldcg(&src[bb * 128 + kq]);
            }
        }
        __syncthreads();
        GEMM_CHUNK(Wq1, W1STR4, 128, 64);        // W_hh1 part, K=512
        __syncthreads();
        if (half) {
            red[(tid - 128) * 4 + 0] = a0; red[(tid - 128) * 4 + 1] = a1;
            red[(tid - 128) * 4 + 2] = a2; red[(tid - 128) * 4 + 3] = a3;
        }
        __syncthreads();
        if (!half) {
            a0 += red[tid * 4 + 0] + bias1[l0];
            a1 += red[tid * 4 + 1] + bias1[l1];
            a2 += red[tid * 4 + 2] + bias1[l2];
            a3 += red[tid * 4 + 3] + bias1[l3];
            float ig = sigf(a0), fg = sigf(a1), gg = tanhf(a2), og = sigf(a3);
            c1 = fg * c1 + ig * gg;
            g_h1[1 - p][b * HID + (r << 2) + jg] = og * tanhf(c1);
        }
        grid_barrier();
    }

    // ---- Final FC: out[b][o] = h1_final . fc_w[o] + fc_b[o] ----
    // Last step t=2047 (p=1) wrote g_h1[0].
    if (tid < 64) {
        int oo = tid >> 5, bb = tid & 31;
        int o = (r << 1) + oo;
        float acc = __ldg(&fcb[o]);
        const float4* hrow = (const float4*)(&g_h1[0][bb * HID]);
        const float4* wrow = (const float4*)(&fcw[o * HID]);
        #pragma unroll 4
        for (int kq = 0; kq < HID / 4; ++kq) {
            float4 hv = __ldcg(&hrow[kq]);
            float4 wv = __ldg(&wrow[kq]);
            acc = fmaf(hv.x, wv.x, acc); acc = fmaf(hv.y, wv.y, acc);
            acc = fmaf(hv.z, wv.z, acc); acc = fmaf(hv.w, wv.w, acc);
        }
        out[bb * ODIM + o] = acc;
    }
}

extern "C" void kernel_launch(void* const* d_in, const int* in_sizes, int n_in,
                              void* d_out, int out_size) {
    const float* x    = (const float*)d_in[0];
    const float* Wih0 = (const float*)d_in[1];
    const float* Whh0 = (const float*)d_in[2];
    const float* bih0 = (const float*)d_in[3];
    const float* bhh0 = (const float*)d_in[4];
    const float* Wih1 = (const float*)d_in[5];
    const float* Whh1 = (const float*)d_in[6];
    const float* bih1 = (const float*)d_in[7];
    const float* bhh1 = (const float*)d_in[8];
    const float* fcw  = (const float*)d_in[9];
    const float* fcb  = (const float*)d_in[10];
    float* out = (float*)d_out;

    const int smem_bytes =
        (16 * W0K + 16 * W1K + BATCH * HXW + 512 + 32) * (int)sizeof(float);
    cudaFuncSetAttribute(lstm_persistent_kernel,
                         cudaFuncAttributeMaxDynamicSharedMemorySize, smem_bytes);

    lstm_persistent_kernel<<<NCTA, NTH, smem_bytes>>>(
        x, Wih0, Whh0, bih0, bhh0, Wih1, Whh1, bih1, bhh1, fcw, fcb, out);
}

// round 3
// speedup vs baseline: 1.2428x; 1.2428x over previous
#include <cuda_runtime.h>

// LSTM_80582176407707 R3: persistent kernel, fused superstep, f32x2 FFMA,
// 16-row register blocking, flag-based grid barrier (1 per step).
// B=32, T=2048, I=256, H=512, O=256. 128 CTAs x 256 threads, 1 CTA/SM.
//
// Superstep s computes layer1(t=s) and layer0(t=s+1) (both depend only on
// h0(s), h1(s-1), x(s+1)), then ONE grid barrier.
// Thread map: lane b = batch (32), warp kc = k-chunk (8). Each thread holds
// 16 f32x2 accumulators per GEMM (all 16 gate rows of this CTA).

#define BATCH   32
#define TSTEPS  2048
#define INDIM   256
#define HID     512
#define ODIM    256
#define NCTA    128
#define NTH     256
#define HXW     516      // padded staging row (floats); 516/4=129 f4 (odd -> conflict-free)
#define HXW4    129
#define W0K     768      // 256 (x) + 512 (h0)
#define W1K     1024     // 512 (h0) + 512 (h1)

typedef unsigned long long u64;
struct alignas(16) u64x2 { u64 lo, hi; };

__device__ float g_h0[2][BATCH * HID];
__device__ float g_h1[2][BATCH * HID];
__device__ volatile unsigned g_arrive[NCTA * 32];   // one flag per CTA, 128B apart

__device__ __forceinline__ u64 fma2(u64 a, u64 b, u64 c) {
    u64 d; asm("fma.rn.f32x2 %0, %1, %2, %3;" : "=l"(d) : "l"(a), "l"(b), "l"(c));
    return d;
}
__device__ __forceinline__ u64 add2(u64 a, u64 b) {
    u64 d; asm("add.rn.f32x2 %0, %1, %2;" : "=l"(d) : "l"(a), "l"(b));
    return d;
}
__device__ __forceinline__ void upk2(u64 v, float& lo, float& hi) {
    asm("mov.b64 {%0, %1}, %2;" : "=f"(lo), "=f"(hi) : "l"(v));
}
__device__ __forceinline__ float sigf(float x) { return 1.0f / (1.0f + __expf(-x)); }

// Distributed flag barrier: 1 release store per CTA, 128 spinner threads each
// poll one CTA's flag. No contended atomics.
__device__ __forceinline__ void flag_barrier(unsigned target, int tid, int r) {
    __syncthreads();
    if (tid == 0) {
        __threadfence();
        g_arrive[r * 32] = target;
    }
    if (tid < NCTA) {
        while ((int)(g_arrive[tid * 32] - target) < 0) { __nanosleep(20); }
    }
    __threadfence();
    __syncthreads();
}

// ---- staging: global h slab [32][512] (b-major) -> hx SMEM ----
#define STAGE_H(SRC) do {                                                      \
    const float4* src4 = (const float4*)(SRC);                                 \
    _Pragma("unroll 4")                                                        \
    for (int i2 = 0; i2 < 16; ++i2) {                                          \
        int idx = i2 * NTH + tid; int bb2 = idx >> 7, kq2 = idx & 127;         \
        hx4[bb2 * HXW4 + kq2] = __ldcg(&src4[bb2 * 128 + kq2]);                \
    } } while (0)

#define STAGE_X(T) do {                                                        \
    const float4* xs4 = (const float4*)x;                                      \
    _Pragma("unroll 4")                                                        \
    for (int i2 = 0; i2 < 8; ++i2) {                                           \
        int idx = i2 * NTH + tid; int bb2 = idx >> 6, kq2 = idx & 63;          \
        hx4[bb2 * HXW4 + kq2] =                                                \
            __ldg(&xs4[bb2 * (TSTEPS * INDIM / 4) + (T) * (INDIM / 4) + kq2]); \
    } } while (0)

// ---- GEMM phases (per-thread: 16 rows, k-chunk = warp kc) ----
// Phase A: h0 slab -> acc1 += W1[:,0:512], acc0 += W0[:,256:768]
#define GEMM_A() do {                                                          \
    const u64x2* hp  = hxq + b * HXW4 + kc * 16;                               \
    const u64x2* w1p = W1q + kc * 16;                                          \
    const u64x2* w0p = W0q + 64 + kc * 16;                                     \
    _Pragma("unroll 4")                                                        \
    for (int i = 0; i < 16; ++i) {                                             \
        u64x2 hv = hp[i];                                                      \
        _Pragma("unroll")                                                      \
        for (int rr = 0; rr < 16; ++rr) {                                      \
            u64x2 w1 = w1p[rr * 256 + i];                                      \
            acc1[rr] = fma2(hv.lo, w1.lo, acc1[rr]);                           \
            acc1[rr] = fma2(hv.hi, w1.hi, acc1[rr]);                           \
            u64x2 w0 = w0p[rr * 192 + i];                                      \
            acc0[rr] = fma2(hv.lo, w0.lo, acc0[rr]);                           \
            acc0[rr] = fma2(hv.hi, w0.hi, acc0[rr]);                           \
        } } } while (0)

// Phase A1 (epilogue): h0 slab -> acc1 only
#define GEMM_A1() do {                                                         \
    const u64x2* hp  = hxq + b * HXW4 + kc * 16;                               \
    const u64x2* w1p = W1q + kc * 16;                                          \
    _Pragma("unroll 4")                                                        \
    for (int i = 0; i < 16; ++i) {                                             \
        u64x2 hv = hp[i];                                                      \
        _Pragma("unroll")                                                      \
        for (int rr = 0; rr < 16; ++rr) {                                      \
            u64x2 w1 = w1p[rr * 256 + i];                                      \
            acc1[rr] = fma2(hv.lo, w1.lo, acc1[rr]);                           \
            acc1[rr] = fma2(hv.hi, w1.hi, acc1[rr]);                           \
        } } } while (0)

// Phase B: h1 slab -> acc1 += W1[:,512:1024]
#define GEMM_B() do {                                                          \
    const u64x2* hp  = hxq + b * HXW4 + kc * 16;                               \
    const u64x2* w1p = W1q + 128 + kc * 16;                                    \
    _Pragma("unroll 4")                                                        \
    for (int i = 0; i < 16; ++i) {                                             \
        u64x2 hv = hp[i];                                                      \
        _Pragma("unroll")                                                      \
        for (int rr = 0; rr < 16; ++rr) {                                      \
            u64x2 w1 = w1p[rr * 256 + i];                                      \
            acc1[rr] = fma2(hv.lo, w1.lo, acc1[rr]);                           \
            acc1[rr] = fma2(hv.hi, w1.hi, acc1[rr]);                           \
        } } } while (0)

// Phase C: x slab (256) -> acc0 += W0[:,0:256]
#define GEMM_C() do {                                                          \
    const u64x2* hp  = hxq + b * HXW4 + kc * 8;                                \
    const u64x2* w0p = W0q + kc * 8;                                           \
    _Pragma("unroll 4")                                                        \
    for (int i = 0; i < 8; ++i) {                                              \
        u64x2 hv = hp[i];                                                      \
        _Pragma("unroll")                                                      \
        for (int rr = 0; rr < 16; ++rr) {                                      \
            u64x2 w0 = w0p[rr * 192 + i];                                      \
            acc0[rr] = fma2(hv.lo, w0.lo, acc0[rr]);                           \
            acc0[rr] = fma2(hv.hi, w0.hi, acc0[rr]);                           \
        } } } while (0)

// Cross-warp reduce + LSTM cell. red layout: [row(32)][kc(8)][b(32)] u64.
__device__ __forceinline__ float cell_update(const u64* red, int rowbase, int bb,
                                             const float* bias, int q, float& c) {
    float gv[4];
    #pragma unroll
    for (int g = 0; g < 4; ++g) {
        int row = rowbase + g * 4 + q;
        const u64* p = red + row * 256 + bb;
        u64 s = p[0];
        #pragma unroll
        for (int k = 1; k < 8; ++k) s = add2(s, p[k * 32]);
        float lo, hi; upk2(s, lo, hi);
        gv[g] = lo + hi + bias[g * 4 + q];
    }
    float ig = sigf(gv[0]), fg = sigf(gv[1]);
    float gg = tanhf(gv[2]), og = sigf(gv[3]);
    c = fg * c + ig * gg;
    return og * tanhf(c);
}

__global__ __launch_bounds__(NTH, 1) void lstm_persistent_kernel(
    const float* __restrict__ x,
    const float* __restrict__ Wih0, const float* __restrict__ Whh0,
    const float* __restrict__ bih0, const float* __restrict__ bhh0,
    const float* __restrict__ Wih1, const float* __restrict__ Whh1,
    const float* __restrict__ bih1, const float* __restrict__ bhh1,
    const float* __restrict__ fcw,  const float* __restrict__ fcb,
    float* __restrict__ out)
{
    extern __shared__ float smem[];
    float* W0    = smem;                   // [16][768]
    float* W1    = W0 + 16 * W0K;          // [16][1024]
    float* hx    = W1 + 16 * W1K;          // [32][516]; aliased as red[32][8][32] u64
    float* bias1 = hx + BATCH * HXW;       // [16]
    float* bias0 = bias1 + 16;             // [16]

    const int tid = threadIdx.x;
    const int r   = blockIdx.x;
    const int b   = tid & 31;              // batch lane
    const int kc  = tid >> 5;              // k-chunk = warp id (0..7)

    unsigned tgt = g_arrive[r * 32];       // epoch base (flags persist across launches)

    // ---- load weight slices: local row l = gate*4 + unit, global row = 512*gate + 4*r + unit
    for (int idx = tid; idx < 16 * W0K; idx += NTH) {
        int l = idx / W0K, k = idx - l * W0K;
        int g = ((l >> 2) << 9) + (r << 2) + (l & 3);
        W0[idx] = (k < INDIM) ? Wih0[g * INDIM + k] : Whh0[g * HID + (k - INDIM)];
    }
    for (int idx = tid; idx < 16 * W1K; idx += NTH) {
        int l = idx >> 10, k = idx & 1023;
        int g = ((l >> 2) << 9) + (r << 2) + (l & 3);
        W1[idx] = (k < HID) ? Wih1[g * HID + k] : Whh1[g * HID + (k - HID)];
    }
    if (tid < 16) {
        int g = ((tid >> 2) << 9) + (r << 2) + (tid & 3);
        bias0[tid] = bih0[g] + bhh0[g];
        bias1[tid] = bih1[g] + bhh1[g];
    }

    float4* hx4 = (float4*)hx;
    const u64x2* hxq = (const u64x2*)hx;
    const u64x2* W0q = (const u64x2*)W0;
    const u64x2* W1q = (const u64x2*)W1;
    u64* red = (u64*)hx;

    float c0 = 0.0f, c1 = 0.0f;            // c0 valid in tid>=128, c1 in tid<128
    const int qc  = (tid & 127) >> 5;      // cell unit index for cell threads
    const int bbc = tid & 31;
    const int unit = (r << 2) + qc;

    u64 acc0[16], acc1[16];

    // ================= PROLOGUE: layer0(t=0), h/c init = 0 =================
    {
        #pragma unroll
        for (int rr = 0; rr < 16; ++rr) acc0[rr] = 0ull;
        STAGE_X(0);
        __syncthreads();
        GEMM_C();
        __syncthreads();
        #pragma unroll
        for (int rr = 0; rr < 16; ++rr) red[(16 + rr) * 256 + kc * 32 + b] = acc0[rr];
        __syncthreads();
        if (tid >= 128) {
            float h = cell_update(red, 16, bbc, bias0, qc, c0);
            g_h0[0][bbc * HID + unit] = h;
        } else {
            g_h1[0][bbc * HID + unit] = 0.0f;   // h1(-1) = 0
        }
        flag_barrier(++tgt, tid, r);
    }

    // ================= MAIN LOOP: superstep s = layer1(s) + layer0(s+1) ====
    #pragma unroll 1
    for (int s = 0; s < TSTEPS - 1; ++s) {
        const int p = s & 1;
        #pragma unroll
        for (int rr = 0; rr < 16; ++rr) { acc0[rr] = 0ull; acc1[rr] = 0ull; }

        STAGE_H(g_h0[p]);                  // h0(s): feeds BOTH layers
        __syncthreads();
        GEMM_A();
        __syncthreads();

        STAGE_H(g_h1[p]);                  // h1(s-1)
        __syncthreads();
        GEMM_B();
        __syncthreads();

        STAGE_X(s + 1);                    // x(s+1)
        __syncthreads();
        GEMM_C();
        __syncthreads();

        #pragma unroll
        for (int rr = 0; rr < 16; ++rr) {
            red[rr * 256 + kc * 32 + b]        = acc1[rr];
            red[(16 + rr) * 256 + kc * 32 + b] = acc0[rr];
        }
        __syncthreads();

        if (tid < 128) {                   // layer1 cell -> h1(s)
            float h = cell_update(red, 0, bbc, bias1, qc, c1);
            g_h1[1 - p][bbc * HID + unit] = h;
        } else {                           // layer0 cell -> h0(s+1)
            float h = cell_update(red, 16, bbc, bias0, qc, c0);
            g_h0[1 - p][bbc * HID + unit] = h;
        }
        flag_barrier(++tgt, tid, r);
    }

    // ================= EPILOGUE: layer1(t=2047) =================
    {
        const int p = (TSTEPS - 1) & 1;    // = 1
        #pragma unroll
        for (int rr = 0; rr < 16; ++rr) acc1[rr] = 0ull;

        STAGE_H(g_h0[p]);
        __syncthreads();
        GEMM_A1();
        __syncthreads();
        STAGE_H(g_h1[p]);
        __syncthreads();
        GEMM_B();
        __syncthreads();

        #pragma unroll
        for (int rr = 0; rr < 16; ++rr) red[rr * 256 + kc * 32 + b] = acc1[rr];
        __syncthreads();
        if (tid < 128) {
            float h = cell_update(red, 0, bbc, bias1, qc, c1);
            g_h1[1 - p][bbc * HID + unit] = h;   // final h1 -> buffer 0
        }
        flag_barrier(++tgt, tid, r);
    }

    // ================= FINAL FC =================
    if (tid < 64) {
        int oo = tid >> 5, bb = tid & 31;
        int o = (r << 1) + oo;
        float acc = __ldg(&fcb[o]);
        const float4* hrow = (const float4*)(&g_h1[0][bb * HID]);
        const float4* wrow = (const float4*)(&fcw[o * HID]);
        #pragma unroll 4
        for (int kq = 0; kq < HID / 4; ++kq) {
            float4 hv = __ldcg(&hrow[kq]);
            float4 wv = __ldg(&wrow[kq]);
            acc = fmaf(hv.x, wv.x, acc); acc = fmaf(hv.y, wv.y, acc);
            acc = fmaf(hv.z, wv.z, acc); acc = fmaf(hv.w, wv.w, acc);
        }
        out[bb * ODIM + o] = acc;
    }
}

extern "C" void kernel_launch(void* const* d_in, const int* in_sizes, int n_in,
                              void* d_out, int out_size) {
    const float* x    = (const float*)d_in[0];
    const float* Wih0 = (const float*)d_in[1];
    const float* Whh0 = (const float*)d_in[2];
    const float* bih0 = (const float*)d_in[3];
    const float* bhh0 = (const float*)d_in[4];
    const float* Wih1 = (const float*)d_in[5];
    const float* Whh1 = (const float*)d_in[6];
    const float* bih1 = (const float*)d_in[7];
    const float* bhh1 = (const float*)d_in[8];
    const float* fcw  = (const float*)d_in[9];
    const float* fcb  = (const float*)d_in[10];
    float* out = (float*)d_out;

    const int smem_bytes =
        (16 * W0K + 16 * W1K + BATCH * HXW + 32) * (int)sizeof(float);
    cudaFuncSetAttribute(lstm_persistent_kernel,
                         cudaFuncAttributeMaxDynamicSharedMemorySize, smem_bytes);

    lstm_persistent_kernel<<<NCTA, NTH, smem_bytes>>>(
        x, Wih0, Whh0, bih0, bhh0, Wih1, Whh1, bih1, bhh1, fcw, fcb, out);
}

// round 4
// speedup vs baseline: 1.8843x; 1.5162x over previous
#include <cuda_runtime.h>

// LSTM_80582176407707 R4: persistent kernel, 512 threads, 4x4 thread tiles,
// k-major h layout read directly from L2 (no SMEM staging), [quad][row]
// SMEM weights, two-pass GEMM (layer1 then layer0), acq_rel flag barrier.
// B=32, T=2048, I=256, H=512, O=256. 128 CTAs, 1/SM.

#define BATCH   32
#define TSTEPS  2048
#define INDIM   256
#define HID     512
#define ODIM    256
#define NCTA    128
#define NTH     512
#define RSTR    514          // red row stride (floats), padded: bank-clean STS

typedef unsigned long long u64;

// h layout: float[buf][q(128)][b(32)][4 comp]  == unit (4q+comp) of batch b
__device__ float    g_h0[2][16384];
__device__ float    g_h1[2][16384];
__device__ float4   g_xT[(size_t)TSTEPS * 2048];   // [t][q(64)][b(32)] float4
__device__ unsigned g_flag[NCTA * 32];

__device__ __forceinline__ u64 fma2(u64 a, u64 b, u64 c) {
    u64 d; asm("fma.rn.f32x2 %0, %1, %2, %3;" : "=l"(d) : "l"(a), "l"(b), "l"(c));
    return d;
}
__device__ __forceinline__ u64 pk(float a, float b) {
    u64 r; asm("mov.b64 %0, {%1, %2};" : "=l"(r) : "f"(a), "f"(b)); return r;
}
__device__ __forceinline__ void upk(u64 v, float& lo, float& hi) {
    asm("mov.b64 {%0, %1}, %2;" : "=f"(lo), "=f"(hi) : "l"(v));
}
__device__ __forceinline__ void fence_gpu() {
    asm volatile("fence.acq_rel.gpu;" ::: "memory");
}
__device__ __forceinline__ void st_flag(unsigned* p, unsigned v) {
    asm volatile("st.relaxed.gpu.u32 [%0], %1;" :: "l"(p), "r"(v) : "memory");
}
__device__ __forceinline__ unsigned ld_flag(unsigned* p) {
    unsigned v; asm volatile("ld.relaxed.gpu.u32 %0, [%1];" : "=r"(v) : "l"(p) : "memory");
    return v;
}
__device__ __forceinline__ float sigf(float x) { return 1.0f / (1.0f + __expf(-x)); }

// h quad load: lanes (rg broadcast, bg 0..7 consecutive) -> 1 line per LDG.128
template <bool CG>
__device__ __forceinline__ void ld_h(const float4* __restrict__ src, int q, int bg,
                                     u64 hlo[4], u64 hhi[4]) {
    #pragma unroll
    for (int j = 0; j < 4; ++j) {
        float4 v = CG ? __ldcg(&src[q * 32 + j * 8 + bg])
                      : __ldg (&src[q * 32 + j * 8 + bg]);
        hlo[j] = pk(v.x, v.y); hhi[j] = pk(v.z, v.w);
    }
}

// one k-quad MMA: 4 weight rows (lanes rg distinct, conflict-free) x 4 batches
__device__ __forceinline__ void mma_q(u64 acc[16], const float4* __restrict__ Ws,
                                      int qbase, int rg,
                                      const u64 hlo[4], const u64 hhi[4]) {
    #pragma unroll
    for (int i = 0; i < 4; ++i) {
        float4 wv = Ws[qbase + i * 4 + rg];
        u64 wl = pk(wv.x, wv.y), wh = pk(wv.z, wv.w);
        #pragma unroll
        for (int j = 0; j < 4; ++j) {
            acc[i * 4 + j] = fma2(hlo[j], wl, acc[i * 4 + j]);
            acc[i * 4 + j] = fma2(hhi[j], wh, acc[i * 4 + j]);
        }
    }
}

// one-time x transpose: x[b][t][i] -> g_xT[t][q][b] float4
__global__ void transpose_x(const float4* __restrict__ x4) {
    int t = blockIdx.x;
    for (int i = threadIdx.x; i < 2048; i += blockDim.x) {
        int q = i >> 5, b = i & 31;
        g_xT[(size_t)t * 2048 + i] = __ldg(&x4[(size_t)b * (TSTEPS * 64) + t * 64 + q]);
    }
}

__global__ __launch_bounds__(NTH, 1) void lstm_persistent_kernel(
    const float* __restrict__ x,
    const float* __restrict__ Wih0, const float* __restrict__ Whh0,
    const float* __restrict__ bih0, const float* __restrict__ bhh0,
    const float* __restrict__ Wih1, const float* __restrict__ Whh1,
    const float* __restrict__ bih1, const float* __restrict__ bhh1,
    const float* __restrict__ fcw,  const float* __restrict__ fcb,
    float* __restrict__ out)
{
    extern __shared__ float4 smemf4[];
    float4* W0s   = smemf4;                // [192 q][16 l]  l = gate*4+unit
    float4* W1s   = W0s + 192 * 16;        // [256 q][16 l]
    float*  red   = (float*)(W1s + 256 * 16);  // [32 rows][RSTR]
    float*  gates = red + 32 * RSTR;       // [32 rows][32 b]
    float*  b1s   = gates + 1024;          // [16]
    float*  b0s   = b1s + 16;              // [16]

    const int tid  = threadIdx.x;
    const int r    = blockIdx.x;
    const int w    = tid >> 5;             // k-chunk warp 0..15
    const int lane = tid & 31;
    const int rg   = lane >> 3;            // row group 0..3
    const int bg   = lane & 7;             // batch group 0..7

    unsigned tgt = ld_flag(&g_flag[r * 32]);

    // ---- weights into SMEM, [quad][row] layout ----
    for (int idx = tid; idx < 192 * 16; idx += NTH) {
        int q = idx >> 4, l = idx & 15;
        int grow = ((l >> 2) << 9) + (r << 2) + (l & 3);
        int k0 = q << 2;
        float4 v;
        if (k0 < INDIM) {
            const float* p = Wih0 + grow * INDIM + k0;
            v.x = p[0]; v.y = p[1]; v.z = p[2]; v.w = p[3];
        } else {
            const float* p = Whh0 + grow * HID + (k0 - INDIM);
            v.x = p[0]; v.y = p[1]; v.z = p[2]; v.w = p[3];
        }
        W0s[idx] = v;
    }
    for (int idx = tid; idx < 256 * 16; idx += NTH) {
        int q = idx >> 4, l = idx & 15;
        int grow = ((l >> 2) << 9) + (r << 2) + (l & 3);
        int k0 = q << 2;
        float4 v;
        if (k0 < HID) {
            const float* p = Wih1 + grow * HID + k0;
            v.x = p[0]; v.y = p[1]; v.z = p[2]; v.w = p[3];
        } else {
            const float* p = Whh1 + grow * HID + (k0 - HID);
            v.x = p[0]; v.y = p[1]; v.z = p[2]; v.w = p[3];
        }
        W1s[idx] = v;
    }
    if (tid < 16) {
        int grow = ((tid >> 2) << 9) + (r << 2) + (tid & 3);
        b0s[tid] = bih0[grow] + bhh0[grow];
        b1s[tid] = bih1[grow] + bhh1[grow];
    }
    // zero h1(-1) (buffer 0), this CTA's slice (units 4r..4r+3)
    if (tid < 128) g_h1[0][r * 128 + tid] = 0.0f;
    __syncthreads();

    float c0 = 0.0f, c1 = 0.0f;            // c1 in tid<128, c0 in tid 128..255
    u64 hlo[4], hhi[4];
    u64 acc[16];

    // =============== PROLOGUE: layer0(t=0) (h0(-1)=0 -> x part only) ========
    {
        #pragma unroll
        for (int n = 0; n < 16; ++n) acc[n] = 0ull;
        const float4* xt = g_xT;           // t = 0
        #pragma unroll
        for (int v = 0; v < 4; ++v) {
            int q = w * 4 + v;
            ld_h<false>(xt, q, bg, hlo, hhi);
            mma_q(acc, W0s, q * 16, rg, hlo, hhi);
        }
        #pragma unroll
        for (int i = 0; i < 4; ++i)
            #pragma unroll
            for (int j = 0; j < 4; ++j) {
                float lo, hi; upk(acc[i * 4 + j], lo, hi);
                red[(16 + i * 4 + rg) * RSTR + w * 32 + j * 8 + bg] = lo + hi;
            }
        __syncthreads();
        {
            int row = tid >> 5, b = tid & 31;
            float s0 = b0s[row];
            #pragma unroll
            for (int k = 0; k < 16; ++k) s0 += red[(16 + row) * RSTR + k * 32 + b];
            gates[(16 + row) * 32 + b] = s0;
        }
        __syncthreads();
        if (tid >= 128 && tid < 256) {
            int u = (tid >> 5) & 3, b = tid & 31;
            float gi = sigf(gates[(16 + u) * 32 + b]);
            float gf = sigf(gates[(20 + u) * 32 + b]);
            float gg = tanhf(gates[(24 + u) * 32 + b]);
            float go = sigf(gates[(28 + u) * 32 + b]);
            c0 = gf * c0 + gi * gg;
            g_h0[0][r * 128 + b * 4 + u] = go * tanhf(c0);
        }
        __syncthreads();
        if (tid == 0) { fence_gpu(); st_flag(&g_flag[r * 32], ++tgt); } else ++tgt;
        if (tid < NCTA) {
            while ((int)(ld_flag(&g_flag[tid * 32]) - tgt) < 0) __nanosleep(32);
            fence_gpu();
        }
        __syncthreads();
    }

    // =============== MAIN LOOP: superstep s = layer1(s) + layer0(s+1) =======
    #pragma unroll 1
    for (int s = 0; s < TSTEPS - 1; ++s) {
        const int p = s & 1;
        const float4* h0p = (const float4*)g_h0[p];
        const float4* h1p = (const float4*)g_h1[p];
        const float4* xt  = g_xT + (size_t)(s + 1) * 2048;

        // ---- pass 1: layer1 gates (K=1024: h0 | h1) ----
        #pragma unroll
        for (int n = 0; n < 16; ++n) acc[n] = 0ull;
        #pragma unroll 2
        for (int u = 0; u < 8; ++u) {
            int q = w * 8 + u;
            ld_h<true>(h0p, q, bg, hlo, hhi);
            mma_q(acc, W1s, q * 16, rg, hlo, hhi);
        }
        #pragma unroll 2
        for (int u = 0; u < 8; ++u) {
            int q = w * 8 + u;
            ld_h<true>(h1p, q, bg, hlo, hhi);
            mma_q(acc, W1s, (128 + q) * 16, rg, hlo, hhi);
        }
        #pragma unroll
        for (int i = 0; i < 4; ++i)
            #pragma unroll
            for (int j = 0; j < 4; ++j) {
                float lo, hi; upk(acc[i * 4 + j], lo, hi);
                red[(i * 4 + rg) * RSTR + w * 32 + j * 8 + bg] = lo + hi;
            }

        // ---- pass 0: layer0 gates for t=s+1 (K=768: x | h0) ----
        #pragma unroll
        for (int n = 0; n < 16; ++n) acc[n] = 0ull;
        #pragma unroll 2
        for (int v = 0; v < 4; ++v) {
            int q = w * 4 + v;
            ld_h<false>(xt, q, bg, hlo, hhi);
            mma_q(acc, W0s, q * 16, rg, hlo, hhi);
        }
        #pragma unroll 2
        for (int u = 0; u < 8; ++u) {
            int q = w * 8 + u;
            ld_h<true>(h0p, q, bg, hlo, hhi);
            mma_q(acc, W0s, (64 + q) * 16, rg, hlo, hhi);
        }
        #pragma unroll
        for (int i = 0; i < 4; ++i)
            #pragma unroll
            for (int j = 0; j < 4; ++j) {
                float lo, hi; upk(acc[i * 4 + j], lo, hi);
                red[(16 + i * 4 + rg) * RSTR + w * 32 + j * 8 + bg] = lo + hi;
            }
        __syncthreads();

        // ---- gate sums (16 partials each) ----
        {
            int row = tid >> 5, b = tid & 31;
            float s1 = b1s[row], s0 = b0s[row];
            #pragma unroll
            for (int k = 0; k < 16; ++k) {
                s1 += red[row * RSTR + k * 32 + b];
                s0 += red[(16 + row) * RSTR + k * 32 + b];
            }
            gates[row * 32 + b]        = s1;
            gates[(16 + row) * 32 + b] = s0;
        }
        __syncthreads();

        // ---- cells ----
        if (tid < 256) {
            int L = tid >> 7, u = (tid >> 5) & 3, b = tid & 31;
            int ro = L * 16;
            float gi = sigf(gates[(ro + u) * 32 + b]);
            float gf = sigf(gates[(ro + 4 + u) * 32 + b]);
            float gg = tanhf(gates[(ro + 8 + u) * 32 + b]);
            float go = sigf(gates[(ro + 12 + u) * 32 + b]);
            if (L == 0) {                  // layer1 -> h1(s)
                c1 = gf * c1 + gi * gg;
                g_h1[1 - p][r * 128 + b * 4 + u] = go * tanhf(c1);
            } else {                       // layer0 -> h0(s+1)
                c0 = gf * c0 + gi * gg;
                g_h0[1 - p][r * 128 + b * 4 + u] = go * tanhf(c0);
            }
        }
        __syncthreads();
        if (tid == 0) { fence_gpu(); st_flag(&g_flag[r * 32], ++tgt); } else ++tgt;
        if (tid < NCTA) {
            while ((int)(ld_flag(&g_flag[tid * 32]) - tgt) < 0) __nanosleep(32);
            fence_gpu();
        }
        __syncthreads();
    }

    // =============== EPILOGUE: layer1(t=2047) ===============
    {
        const int p = (TSTEPS - 1) & 1;    // 1
        const float4* h0p = (const float4*)g_h0[p];
        const float4* h1p = (const float4*)g_h1[p];
        #pragma unroll
        for (int n = 0; n < 16; ++n) acc[n] = 0ull;
        #pragma unroll 2
        for (int u = 0; u < 8; ++u) {
            int q = w * 8 + u;
            ld_h<true>(h0p, q, bg, hlo, hhi);
            mma_q(acc, W1s, q * 16, rg, hlo, hhi);
        }
        #pragma unroll 2
        for (int u = 0; u < 8; ++u) {
            int q = w * 8 + u;
            ld_h<true>(h1p, q, bg, hlo, hhi);
            mma_q(acc, W1s, (128 + q) * 16, rg, hlo, hhi);
        }
        #pragma unroll
        for (int i = 0; i < 4; ++i)
            #pragma unroll
            for (int j = 0; j < 4; ++j) {
                float lo, hi; upk(acc[i * 4 + j], lo, hi);
                red[(i * 4 + rg) * RSTR + w * 32 + j * 8 + bg] = lo + hi;
            }
        __syncthreads();
        {
            int row = tid >> 5, b = tid & 31;
            float s1 = b1s[row];
            #pragma unroll
            for (int k = 0; k < 16; ++k) s1 += red[row * RSTR + k * 32 + b];
            gates[row * 32 + b] = s1;
        }
        __syncthreads();
        if (tid < 128) {
            int u = (tid >> 5) & 3, b = tid & 31;
            float gi = sigf(gates[(u) * 32 + b]);
            float gf = sigf(gates[(4 + u) * 32 + b]);
            float gg = tanhf(gates[(8 + u) * 32 + b]);
            float go = sigf(gates[(12 + u) * 32 + b]);
            c1 = gf * c1 + gi * gg;
            g_h1[1 - p][r * 128 + b * 4 + u] = go * tanhf(c1);  // -> buffer 0
        }
        __syncthreads();
        if (tid == 0) { fence_gpu(); st_flag(&g_flag[r * 32], ++tgt); } else ++tgt;
        if (tid < NCTA) {
            while ((int)(ld_flag(&g_flag[tid * 32]) - tgt) < 0) __nanosleep(32);
            fence_gpu();
        }
        __syncthreads();
    }

    // =============== FINAL FC ===============
    if (tid < 64) {
        int oo = tid >> 5, b = tid & 31;
        int o = (r << 1) + oo;
        float accf = __ldg(&fcb[o]);
        const float4* h1f = (const float4*)g_h1[0];
        const float4* w4  = (const float4*)(fcw + o * HID);
        #pragma unroll 4
        for (int q = 0; q < 128; ++q) {
            float4 hv = __ldcg(&h1f[q * 32 + b]);   // units 4q..4q+3 of batch b
            float4 wv = __ldg(&w4[q]);
            accf = fmaf(hv.x, wv.x, accf); accf = fmaf(hv.y, wv.y, accf);
            accf = fmaf(hv.z, wv.z, accf); accf = fmaf(hv.w, wv.w, accf);
        }
        out[b * ODIM + o] = accf;
    }
}

extern "C" void kernel_launch(void* const* d_in, const int* in_sizes, int n_in,
                              void* d_out, int out_size) {
    const float* x    = (const float*)d_in[0];
    const float* Wih0 = (const float*)d_in[1];
    const float* Whh0 = (const float*)d_in[2];
    const float* bih0 = (const float*)d_in[3];
    const float* bhh0 = (const float*)d_in[4];
    const float* Wih1 = (const float*)d_in[5];
    const float* Whh1 = (const float*)d_in[6];
    const float* bih1 = (const float*)d_in[7];
    const float* bhh1 = (const float*)d_in[8];
    const float* fcw  = (const float*)d_in[9];
    const float* fcb  = (const float*)d_in[10];
    float* out = (float*)d_out;

    transpose_x<<<TSTEPS, 256>>>((const float4*)x);

    const int smem_bytes = (192 * 16 + 256 * 16) * 16 +
                           (32 * RSTR + 1024 + 32) * 4;
    cudaFuncSetAttribute(lstm_persistent_kernel,
                         cudaFuncAttributeMaxDynamicSharedMemorySize, smem_bytes);
    lstm_persistent_kernel<<<NCTA, NTH, smem_bytes>>>(
        x, Wih0, Whh0, bih0, bhh0, Wih1, Whh1, bih1, bhh1, fcw, fcb, out);
}

// round 5
// speedup vs baseline: 2.1541x; 1.1432x over previous
#include <cuda_runtime.h>

// LSTM_80582176407707 R5: R4 + (a) conflict-free partial stores (RSTR 520),
// (b) x-projection GEMM hoisted into the barrier-wait window (red2 region).
// B=32, T=2048, I=256, H=512, O=256. 128 CTAs x 512 threads, 1 CTA/SM.

#define BATCH   32
#define TSTEPS  2048
#define INDIM   256
#define HID     512
#define ODIM    256
#define NCTA    128
#define NTH     512
#define RSTR    520          // red row stride (floats): rows 8 banks apart ->
                             // STS lanes (rg,bg) hit 32 distinct banks

typedef unsigned long long u64;

// h layout: float[buf][q(128)][b(32)][4 comp]  == unit (4q+comp) of batch b
__device__ float    g_h0[2][16384];
__device__ float    g_h1[2][16384];
__device__ float4   g_xT[(size_t)TSTEPS * 2048];   // [t][q(64)][b(32)] float4
__device__ unsigned g_flag[NCTA * 32];

__device__ __forceinline__ u64 fma2(u64 a, u64 b, u64 c) {
    u64 d; asm("fma.rn.f32x2 %0, %1, %2, %3;" : "=l"(d) : "l"(a), "l"(b), "l"(c));
    return d;
}
__device__ __forceinline__ u64 pk(float a, float b) {
    u64 r; asm("mov.b64 %0, {%1, %2};" : "=l"(r) : "f"(a), "f"(b)); return r;
}
__device__ __forceinline__ void upk(u64 v, float& lo, float& hi) {
    asm("mov.b64 {%0, %1}, %2;" : "=f"(lo), "=f"(hi) : "l"(v));
}
__device__ __forceinline__ void fence_gpu() {
    asm volatile("fence.acq_rel.gpu;" ::: "memory");
}
__device__ __forceinline__ void st_flag(unsigned* p, unsigned v) {
    asm volatile("st.relaxed.gpu.u32 [%0], %1;" :: "l"(p), "r"(v) : "memory");
}
__device__ __forceinline__ unsigned ld_flag(unsigned* p) {
    unsigned v; asm volatile("ld.relaxed.gpu.u32 %0, [%1];" : "=r"(v) : "l"(p) : "memory");
    return v;
}
__device__ __forceinline__ float sigf(float x) { return 1.0f / (1.0f + __expf(-x)); }

// h quad load: lanes (rg broadcast, bg 0..7 consecutive) -> 1 line per LDG.128
template <bool CG>
__device__ __forceinline__ void ld_h(const float4* __restrict__ src, int q, int bg,
                                     u64 hlo[4], u64 hhi[4]) {
    #pragma unroll
    for (int j = 0; j < 4; ++j) {
        float4 v = CG ? __ldcg(&src[q * 32 + j * 8 + bg])
                      : __ldg (&src[q * 32 + j * 8 + bg]);
        hlo[j] = pk(v.x, v.y); hhi[j] = pk(v.z, v.w);
    }
}

// one k-quad MMA: 4 weight rows (lanes rg distinct, conflict-free) x 4 batches
__device__ __forceinline__ void mma_q(u64 acc[16], const float4* __restrict__ Ws,
                                      int qbase, int rg,
                                      const u64 hlo[4], const u64 hhi[4]) {
    #pragma unroll
    for (int i = 0; i < 4; ++i) {
        float4 wv = Ws[qbase + i * 4 + rg];
        u64 wl = pk(wv.x, wv.y), wh = pk(wv.z, wv.w);
        #pragma unroll
        for (int j = 0; j < 4; ++j) {
            acc[i * 4 + j] = fma2(hlo[j], wl, acc[i * 4 + j]);
            acc[i * 4 + j] = fma2(hhi[j], wh, acc[i * 4 + j]);
        }
    }
}

// one-time x transpose: x[b][t][i] -> g_xT[t][q][b] float4
__global__ void transpose_x(const float4* __restrict__ x4) {
    int t = blockIdx.x;
    for (int i = threadIdx.x; i < 2048; i += blockDim.x) {
        int q = i >> 5, b = i & 31;
        g_xT[(size_t)t * 2048 + i] = __ldg(&x4[(size_t)b * (TSTEPS * 64) + t * 64 + q]);
    }
}

// store 4x4 accumulator tile to red rows [rowbase, rowbase+16)
#define STORE_ACC(ROWBASE)                                                     \
    do {                                                                       \
        _Pragma("unroll")                                                      \
        for (int i = 0; i < 4; ++i)                                            \
            _Pragma("unroll")                                                  \
            for (int j = 0; j < 4; ++j) {                                      \
                float lo, hi; upk(acc[i * 4 + j], lo, hi);                     \
                red[((ROWBASE) + i * 4 + rg) * RSTR + w * 32 + j * 8 + bg]     \
                    = lo + hi;                                                 \
            }                                                                  \
    } while (0)

#define BARRIER_PUBLISH()                                                      \
    do { if (tid == 0) { fence_gpu(); st_flag(&g_flag[r * 32], tgt + 1); }     \
         ++tgt; } while (0)

#define BARRIER_POLL()                                                         \
    do { if (tid < NCTA) {                                                     \
             while ((int)(ld_flag(&g_flag[tid * 32]) - tgt) < 0)               \
                 __nanosleep(32);                                              \
             fence_gpu();                                                      \
         }                                                                     \
         __syncthreads(); } while (0)

__global__ __launch_bounds__(NTH, 1) void lstm_persistent_kernel(
    const float* __restrict__ x,
    const float* __restrict__ Wih0, const float* __restrict__ Whh0,
    const float* __restrict__ bih0, const float* __restrict__ bhh0,
    const float* __restrict__ Wih1, const float* __restrict__ Whh1,
    const float* __restrict__ bih1, const float* __restrict__ bhh1,
    const float* __restrict__ fcw,  const float* __restrict__ fcb,
    float* __restrict__ out)
{
    extern __shared__ float4 smemf4[];
    float4* W0s   = smemf4;                // [192 q][16 l]  l = gate*4+unit
    float4* W1s   = W0s + 192 * 16;        // [256 q][16 l]
    float*  red   = (float*)(W1s + 256 * 16);  // [48 rows][RSTR]
                                           // rows 0-15: L1 partials
                                           // rows 16-31: L0 h-part partials
                                           // rows 32-47: L0 x-part partials (hoisted)
    float*  gates = red + 48 * RSTR;       // [32 rows][32 b]
    float*  b1s   = gates + 1024;          // [16]
    float*  b0s   = b1s + 16;              // [16]

    const int tid  = threadIdx.x;
    const int r    = blockIdx.x;
    const int w    = tid >> 5;             // k-chunk warp 0..15
    const int lane = tid & 31;
    const int rg   = lane >> 3;            // row group 0..3
    const int bg   = lane & 7;             // batch group 0..7

    unsigned tgt = ld_flag(&g_flag[r * 32]);

    // ---- weights into SMEM, [quad][row] layout ----
    for (int idx = tid; idx < 192 * 16; idx += NTH) {
        int q = idx >> 4, l = idx & 15;
        int grow = ((l >> 2) << 9) + (r << 2) + (l & 3);
        int k0 = q << 2;
        float4 v;
        if (k0 < INDIM) {
            const float* p = Wih0 + grow * INDIM + k0;
            v.x = p[0]; v.y = p[1]; v.z = p[2]; v.w = p[3];
        } else {
            const float* p = Whh0 + grow * HID + (k0 - INDIM);
            v.x = p[0]; v.y = p[1]; v.z = p[2]; v.w = p[3];
        }
        W0s[idx] = v;
    }
    for (int idx = tid; idx < 256 * 16; idx += NTH) {
        int q = idx >> 4, l = idx & 15;
        int grow = ((l >> 2) << 9) + (r << 2) + (l & 3);
        int k0 = q << 2;
        float4 v;
        if (k0 < HID) {
            const float* p = Wih1 + grow * HID + k0;
            v.x = p[0]; v.y = p[1]; v.z = p[2]; v.w = p[3];
        } else {
            const float* p = Whh1 + grow * HID + (k0 - HID);
            v.x = p[0]; v.y = p[1]; v.z = p[2]; v.w = p[3];
        }
        W1s[idx] = v;
    }
    if (tid < 16) {
        int grow = ((tid >> 2) << 9) + (r << 2) + (tid & 3);
        b0s[tid] = bih0[grow] + bhh0[grow];
        b1s[tid] = bih1[grow] + bhh1[grow];
    }
    // zero h1(-1) (buffer 0), this CTA's slice (units 4r..4r+3)
    if (tid < 128) g_h1[0][r * 128 + tid] = 0.0f;
    __syncthreads();

    float c0 = 0.0f, c1 = 0.0f;            // c1 in tid<128, c0 in tid 128..255
    u64 hlo[4], hhi[4];
    u64 acc[16];

    // =============== PROLOGUE: layer0(t=0) (h0(-1)=0 -> x part only) ========
    {
        #pragma unroll
        for (int n = 0; n < 16; ++n) acc[n] = 0ull;
        #pragma unroll
        for (int v = 0; v < 4; ++v) {
            int q = w * 4 + v;
            ld_h<false>(g_xT, q, bg, hlo, hhi);      // t = 0
            mma_q(acc, W0s, q * 16, rg, hlo, hhi);
        }
        STORE_ACC(16);
        __syncthreads();
        {
            int row = tid >> 5, b = tid & 31;
            float s0 = b0s[row];
            #pragma unroll
            for (int k = 0; k < 16; ++k) s0 += red[(16 + row) * RSTR + k * 32 + b];
            gates[(16 + row) * 32 + b] = s0;
        }
        __syncthreads();
        if (tid >= 128 && tid < 256) {
            int u = (tid >> 5) & 3, b = tid & 31;
            float gi = sigf(gates[(16 + u) * 32 + b]);
            float gf = sigf(gates[(20 + u) * 32 + b]);
            float gg = tanhf(gates[(24 + u) * 32 + b]);
            float go = sigf(gates[(28 + u) * 32 + b]);
            c0 = gf * c0 + gi * gg;
            g_h0[0][r * 128 + b * 4 + u] = go * tanhf(c0);
        }
        __syncthreads();
        BARRIER_PUBLISH();
        // hoisted: x(1) projection partials for superstep 0 -> red rows 32-47
        {
            #pragma unroll
            for (int n = 0; n < 16; ++n) acc[n] = 0ull;
            const float4* xt = g_xT + 2048;          // t = 1
            #pragma unroll
            for (int v = 0; v < 4; ++v) {
                int q = w * 4 + v;
                ld_h<false>(xt, q, bg, hlo, hhi);
                mma_q(acc, W0s, q * 16, rg, hlo, hhi);
            }
            STORE_ACC(32);
        }
        BARRIER_POLL();
    }

    // =============== MAIN LOOP: superstep s = layer1(s) + layer0(s+1) =======
    // red2 (rows 32-47) holds x(s+1) partials computed during superstep s-1.
    #pragma unroll 1
    for (int s = 0; s < TSTEPS - 1; ++s) {
        const int p = s & 1;
        const float4* h0p = (const float4*)g_h0[p];
        const float4* h1p = (const float4*)g_h1[p];

        // ---- pass 1: layer1 gates (K=1024: h0 | h1) ----
        #pragma unroll
        for (int n = 0; n < 16; ++n) acc[n] = 0ull;
        #pragma unroll 2
        for (int u = 0; u < 8; ++u) {
            int q = w * 8 + u;
            ld_h<true>(h0p, q, bg, hlo, hhi);
            mma_q(acc, W1s, q * 16, rg, hlo, hhi);
        }
        #pragma unroll 2
        for (int u = 0; u < 8; ++u) {
            int q = w * 8 + u;
            ld_h<true>(h1p, q, bg, hlo, hhi);
            mma_q(acc, W1s, (128 + q) * 16, rg, hlo, hhi);
        }
        STORE_ACC(0);

        // ---- pass 0: layer0(s+1) h-part only (K=512; x-part precomputed) ----
        #pragma unroll
        for (int n = 0; n < 16; ++n) acc[n] = 0ull;
        #pragma unroll 2
        for (int u = 0; u < 8; ++u) {
            int q = w * 8 + u;
            ld_h<true>(h0p, q, bg, hlo, hhi);
            mma_q(acc, W0s, (64 + q) * 16, rg, hlo, hhi);
        }
        STORE_ACC(16);
        __syncthreads();

        // ---- gate sums ----
        {
            int row = tid >> 5, b = tid & 31;
            float s1 = b1s[row], s0 = b0s[row];
            #pragma unroll
            for (int k = 0; k < 16; ++k) {
                s1 += red[row * RSTR + k * 32 + b];
                s0 += red[(16 + row) * RSTR + k * 32 + b]
                    + red[(32 + row) * RSTR + k * 32 + b];
            }
            gates[row * 32 + b]        = s1;
            gates[(16 + row) * 32 + b] = s0;
        }
        __syncthreads();

        // ---- cells ----
        if (tid < 256) {
            int L = tid >> 7, u = (tid >> 5) & 3, b = tid & 31;
            int ro = L * 16;
            float gi = sigf(gates[(ro + u) * 32 + b]);
            float gf = sigf(gates[(ro + 4 + u) * 32 + b]);
            float gg = tanhf(gates[(ro + 8 + u) * 32 + b]);
            float go = sigf(gates[(ro + 12 + u) * 32 + b]);
            if (L == 0) {                  // layer1 -> h1(s)
                c1 = gf * c1 + gi * gg;
                g_h1[1 - p][r * 128 + b * 4 + u] = go * tanhf(c1);
            } else {                       // layer0 -> h0(s+1)
                c0 = gf * c0 + gi * gg;
                g_h0[1 - p][r * 128 + b * 4 + u] = go * tanhf(c0);
            }
        }
        __syncthreads();
        BARRIER_PUBLISH();

        // ---- hoisted x(s+2) projection during barrier wait ----
        if (s < TSTEPS - 2) {
            #pragma unroll
            for (int n = 0; n < 16; ++n) acc[n] = 0ull;
            const float4* xt = g_xT + (size_t)(s + 2) * 2048;
            #pragma unroll
            for (int v = 0; v < 4; ++v) {
                int q = w * 4 + v;
                ld_h<false>(xt, q, bg, hlo, hhi);
                mma_q(acc, W0s, q * 16, rg, hlo, hhi);
            }
            STORE_ACC(32);
        }
        BARRIER_POLL();
    }

    // =============== EPILOGUE: layer1(t=2047) ===============
    {
        const int p = (TSTEPS - 1) & 1;    // 1
        const float4* h0p = (const float4*)g_h0[p];
        const float4* h1p = (const float4*)g_h1[p];
        #pragma unroll
        for (int n = 0; n < 16; ++n) acc[n] = 0ull;
        #pragma unroll 2
        for (int u = 0; u < 8; ++u) {
            int q = w * 8 + u;
            ld_h<true>(h0p, q, bg, hlo, hhi);
            mma_q(acc, W1s, q * 16, rg, hlo, hhi);
        }
        #pragma unroll 2
        for (int u = 0; u < 8; ++u) {
            int q = w * 8 + u;
            ld_h<true>(h1p, q, bg, hlo, hhi);
            mma_q(acc, W1s, (128 + q) * 16, rg, hlo, hhi);
        }
        STORE_ACC(0);
        __syncthreads();
        {
            int row = tid >> 5, b = tid & 31;
            float s1 = b1s[row];
            #pragma unroll
            for (int k = 0; k < 16; ++k) s1 += red[row * RSTR + k * 32 + b];
            gates[row * 32 + b] = s1;
        }
        __syncthreads();
        if (tid < 128) {
            int u = (tid >> 5) & 3, b = tid & 31;
            float gi = sigf(gates[(u) * 32 + b]);
            float gf = sigf(gates[(4 + u) * 32 + b]);
            float gg = tanhf(gates[(8 + u) * 32 + b]);
            float go = sigf(gates[(12 + u) * 32 + b]);
            c1 = gf * c1 + gi * gg;
            g_h1[1 - p][r * 128 + b * 4 + u] = go * tanhf(c1);  // -> buffer 0
        }
        __syncthreads();
        BARRIER_PUBLISH();
        BARRIER_POLL();
    }

    // =============== FINAL FC ===============
    if (tid < 64) {
        int oo = tid >> 5, b = tid & 31;
        int o = (r << 1) + oo;
        float accf = __ldg(&fcb[o]);
        const float4* h1f = (const float4*)g_h1[0];
        const float4* w4  = (const float4*)(fcw + o * HID);
        #pragma unroll 4
        for (int q = 0; q < 128; ++q) {
            float4 hv = __ldcg(&h1f[q * 32 + b]);   // units 4q..4q+3 of batch b
            float4 wv = __ldg(&w4[q]);
            accf = fmaf(hv.x, wv.x, accf); accf = fmaf(hv.y, wv.y, accf);
            accf = fmaf(hv.z, wv.z, accf); accf = fmaf(hv.w, wv.w, accf);
        }
        out[b * ODIM + o] = accf;
    }
}

extern "C" void kernel_launch(void* const* d_in, const int* in_sizes, int n_in,
                              void* d_out, int out_size) {
    const float* x    = (const float*)d_in[0];
    const float* Wih0 = (const float*)d_in[1];
    const float* Whh0 = (const float*)d_in[2];
    const float* bih0 = (const float*)d_in[3];
    const float* bhh0 = (const float*)d_in[4];
    const float* Wih1 = (const float*)d_in[5];
    const float* Whh1 = (const float*)d_in[6];
    const float* bih1 = (const float*)d_in[7];
    const float* bhh1 = (const float*)d_in[8];
    const float* fcw  = (const float*)d_in[9];
    const float* fcb  = (const float*)d_in[10];
    float* out = (float*)d_out;

    transpose_x<<<TSTEPS, 256>>>((const float4*)x);

    const int smem_bytes = (192 * 16 + 256 * 16) * 16 +
                           (48 * RSTR + 1024 + 32) * 4;   // 218752 B
    cudaFuncSetAttribute(lstm_persistent_kernel,
                         cudaFuncAttributeMaxDynamicSharedMemorySize, smem_bytes);
    lstm_persistent_kernel<<<NCTA, NTH, smem_bytes>>>(
        x, Wih0, Whh0, bih0, bhh0, Wih1, Whh1, bih1, bhh1, fcw, fcb, out);
}